// round 14
// baseline (speedup 1.0000x reference)
#include <cuda_runtime.h>
#include <cuda_fp16.h>
#include <cstdint>

// Problem shape (fixed by the dataset)
#define Bdim 4
#define Ldim 4096
#define Ddim 1024
#define Mrows (Bdim * Ldim)          // 16384
#define BLD ((size_t)Bdim * Ldim * Ddim)
#define NCHUNK 512
#define CLEN (Ldim / NCHUNK)         // 8
#define KDIM 1024
#define BKT 64
#define NKT (KDIM / BKT)             // 16
#define RS 72                        // smem row stride in halves (LDSM conflict-free)
#define TILE_H (128 * RS)            // halves per smem tile (9216)

// ---------------- scratch (static device arrays; no allocation) -------------
__device__ __half g_norm[(size_t)Mrows * Ddim];  // ctx_norm (fp16)
__device__ float  g_alpha[(size_t)Mrows * Ddim]; // alphas (fp32: a~1 needs precision)
__device__ __half g_x[(size_t)Mrows * Ddim];     // gated recurrence input x_t (fp16)
__device__ __half g_f[(size_t)Mrows * Ddim];     // fetched (fp16, GEMM3 input)
__device__ float  g_Xagg[(size_t)Bdim * NCHUNK * Ddim];
__device__ float  g_Aagg[(size_t)Bdim * NCHUNK * Ddim];
__device__ float  g_carry[(size_t)Bdim * NCHUNK * Ddim];
__device__ __half g_Wt[3][(size_t)Ddim * Ddim];  // transposed fp16 weights [N][K]

__device__ __forceinline__ float sigmoidf_(float z) {
    return 1.0f / (1.0f + __expf(-z));
}
__device__ __forceinline__ uint32_t smem_u32(const void* p) {
    return (uint32_t)__cvta_generic_to_shared(p);
}
#define CP16(dst, src) \
    asm volatile("cp.async.cg.shared.global [%0], [%1], 16;\n" ::"r"(dst), "l"(src))
#define LDSM4(r0, r1, r2, r3, a)                                             \
    asm volatile("ldmatrix.sync.aligned.m8n8.x4.shared.b16 {%0,%1,%2,%3}, [%4];" \
                 : "=r"(r0), "=r"(r1), "=r"(r2), "=r"(r3) : "r"(a))

// ------- rmsnorm (fp16 output) + fused alpha_logits pass-through copy --------
__global__ void rms_kernel(const float* __restrict__ ctx,
                           const float* __restrict__ g,
                           __half* __restrict__ o,
                           const float* __restrict__ al,
                           float* __restrict__ o_al) {
    int row = blockIdx.x, tid = threadIdx.x;
    const float4* src = (const float4*)(ctx + (size_t)row * Ddim);
    const float4* asrc = (const float4*)(al + (size_t)row * Ddim);
    float4 xv = src[tid];
    float4 av = asrc[tid];  // independent load stream
    float ss = xv.x * xv.x + xv.y * xv.y + xv.z * xv.z + xv.w * xv.w;
#pragma unroll
    for (int off = 16; off > 0; off >>= 1)
        ss += __shfl_xor_sync(0xffffffffu, ss, off);
    __shared__ float ws[8];
    if ((tid & 31) == 0) ws[tid >> 5] = ss;
    ((float4*)(o_al + (size_t)row * Ddim))[tid] = av;  // copy while waiting
    __syncthreads();
    float tot = ws[0] + ws[1] + ws[2] + ws[3] + ws[4] + ws[5] + ws[6] + ws[7];
    float r = rsqrtf(tot * (1.0f / Ddim) + 1e-6f);
    float4 gv = ((const float4*)g)[tid];
    __half2 h01 = __floats2half2_rn(xv.x * r * gv.x, xv.y * r * gv.y);
    __half2 h23 = __floats2half2_rn(xv.z * r * gv.z, xv.w * r * gv.w);
    __half2* dst = (__half2*)(o + (size_t)row * Ddim);
    dst[tid * 2] = h01;
    dst[tid * 2 + 1] = h23;
}

// -------- weight transpose ([K,N] fp32 -> [N,K] fp16), all 3 in one launch ---
__global__ void transpose_kernel(const float* __restrict__ W0,
                                 const float* __restrict__ W1,
                                 const float* __restrict__ W2,
                                 __half* __restrict__ Wt) {
    __shared__ float tile[32][33];
    const float* W = (blockIdx.z == 0) ? W0 : (blockIdx.z == 1) ? W1 : W2;
    __half* Wo = Wt + (size_t)blockIdx.z * Ddim * Ddim;
    int x = blockIdx.x * 32 + threadIdx.x;
    int y = blockIdx.y * 32 + threadIdx.y;
#pragma unroll
    for (int j = 0; j < 32; j += 8)
        tile[threadIdx.y + j][threadIdx.x] = W[(size_t)(y + j) * Ddim + x];
    __syncthreads();
    int nx = blockIdx.y * 32 + threadIdx.x;
    int ny = blockIdx.x * 32 + threadIdx.y;
#pragma unroll
    for (int j = 0; j < 32; j += 8)
        Wo[(size_t)(ny + j) * Ddim + nx] = __float2half_rn(tile[threadIdx.x][threadIdx.y + j]);
}

// ================= FP16 mma.sync GEMM (m16n8k16, ldmatrix, BKT=64) ===========
// R6-proven config: 3 stages, SMEM K-minor row stride RS=72 halves.
// FUSED (512 thr): wg0 -> C1 = A*W1t, wg1 -> C2 = A*W2t; aux (v) L2-prefetched;
//   symmetric split epilogue (wg0 emits h==0 rows, wg1 h==1 rows) which ALSO
//   computes per-8-row-chunk scan aggregates (X, A) via warp shfl (scan_p1 fused).
// !FUSED (256 thr): out1 = aux + silu(C1 + b1); ctx tile L2-prefetched.
template <bool FUSED>
__global__ void __launch_bounds__(FUSED ? 512 : 256, FUSED ? 1 : 2) gemm_mma(
    const __half* __restrict__ A, const __half* __restrict__ W1t,
    const __half* __restrict__ W2t,
    const float* __restrict__ bias1, const float* __restrict__ bias2,
    const float* __restrict__ aux,
    float* __restrict__ out1, __half* __restrict__ out2,
    float* __restrict__ out_v,
    float* __restrict__ Xagg, float* __restrict__ Aagg) {
    constexpr int NT = FUSED ? 512 : 256;
    constexpr int NTILES = FUSED ? 3 : 2;
    constexpr int STAGE_H = NTILES * TILE_H;
    extern __shared__ __half smh[];

    const int tid = threadIdx.x;
    const int warp = tid >> 5, lane = tid & 31;
    const int wg = FUSED ? (warp >> 3) : 0;   // warpgroup (0/1)
    const int w8 = warp & 7;
    const int wm = w8 >> 1, wn = w8 & 1;      // 4x2 warp grid over 128x128
    const int gid = lane >> 2, tig = lane & 3;
    const int m0 = blockIdx.y * 128, n0 = blockIdx.x * 128;

    float acc[2][8][4];
#pragma unroll
    for (int i = 0; i < 2; i++)
#pragma unroll
        for (int j = 0; j < 8; j++)
#pragma unroll
            for (int k = 0; k < 4; k++) acc[i][j][k] = 0.0f;

    // ---- ldmatrix lane-address offsets (halves, relative to tile, excl. ko)
    const int lq = lane >> 3, lr = lane & 7;
    uint32_t a_loff[2], b_loff[4];
#pragma unroll
    for (int mf = 0; mf < 2; mf++)
        a_loff[mf] = (uint32_t)((wm * 32 + mf * 16 + lr + (lq & 1) * 8) * RS +
                                (lq >> 1) * 8);
#pragma unroll
    for (int p = 0; p < 4; p++)
        b_loff[p] = (uint32_t)((wn * 64 + p * 16 + lr + (lq >> 1) * 8) * RS +
                               (lq & 1) * 8);

    // warm L2 with the aux tile (v for FUSED, ctx for !FUSED): 512 x 128B lines
    {
#pragma unroll
        for (int q = 0; q < 512 / NT; q++) {
            int i = tid + q * NT;
            int row = i >> 2, c = (i & 3) * 32;
            asm volatile("prefetch.global.L2 [%0];" ::
                         "l"(aux + (size_t)(m0 + row) * Ddim + n0 + c));
        }
    }

    // 1024 16B-chunks per tile (128 rows x 8 chunks of 8 halves)
    auto ld_tile = [&](const __half* gsrc, __half* sdst, int row_off, int k0) {
#pragma unroll
        for (int j = 0; j < 1024 / NT; j++) {
            int i = tid + j * NT;
            int row = i >> 3, c = i & 7;
            CP16(smem_u32(sdst + row * RS + c * 8),
                 gsrc + (size_t)(row_off + row) * KDIM + k0 + c * 8);
        }
    };
    auto load_stage = [&](int kt, int s) {
        const int k0 = kt * BKT;
        __half* sb = smh + s * STAGE_H;
        ld_tile(A, sb, m0, k0);
        ld_tile(W1t, sb + TILE_H, n0, k0);
        if (FUSED) ld_tile(W2t, sb + 2 * TILE_H, n0, k0);
        asm volatile("cp.async.commit_group;\n");
    };

    load_stage(0, 0);
    load_stage(1, 1);

    const uint32_t smbase = smem_u32(smh);
    int s = 0;
    for (int kt = 0; kt < NKT; kt++) {
        if (kt >= NKT - 1)
            asm volatile("cp.async.wait_group 0;\n");
        else
            asm volatile("cp.async.wait_group 1;\n");
        __syncthreads();
        if (kt + 2 < NKT) {
            int s2 = s + 2;
            if (s2 >= 3) s2 -= 3;
            load_stage(kt + 2, s2);
        }

        const uint32_t a_base = smbase + s * (STAGE_H * 2);
        const uint32_t b_base = a_base + (1 + wg) * (TILE_H * 2);
#pragma unroll
        for (int ks = 0; ks < 4; ks++) {
            const int ko2 = ks * 32;  // k offset in bytes (16 halves)
            uint32_t af[2][4];
#pragma unroll
            for (int mf = 0; mf < 2; mf++)
                LDSM4(af[mf][0], af[mf][1], af[mf][2], af[mf][3],
                      a_base + a_loff[mf] * 2 + ko2);
#pragma unroll
            for (int p = 0; p < 4; p++) {
                uint32_t b0, b1, b2, b3;
                LDSM4(b0, b1, b2, b3, b_base + b_loff[p] * 2 + ko2);
#pragma unroll
                for (int mf = 0; mf < 2; mf++) {
                    asm volatile(
                        "mma.sync.aligned.m16n8k16.row.col.f32.f16.f16.f32 "
                        "{%0,%1,%2,%3}, {%4,%5,%6,%7}, {%8,%9}, {%0,%1,%2,%3};\n"
                        : "+f"(acc[mf][2 * p][0]), "+f"(acc[mf][2 * p][1]),
                          "+f"(acc[mf][2 * p][2]), "+f"(acc[mf][2 * p][3])
                        : "r"(af[mf][0]), "r"(af[mf][1]), "r"(af[mf][2]),
                          "r"(af[mf][3]), "r"(b0), "r"(b1));
                    asm volatile(
                        "mma.sync.aligned.m16n8k16.row.col.f32.f16.f16.f32 "
                        "{%0,%1,%2,%3}, {%4,%5,%6,%7}, {%8,%9}, {%0,%1,%2,%3};\n"
                        : "+f"(acc[mf][2 * p + 1][0]), "+f"(acc[mf][2 * p + 1][1]),
                          "+f"(acc[mf][2 * p + 1][2]), "+f"(acc[mf][2 * p + 1][3])
                        : "r"(af[mf][0]), "r"(af[mf][1]), "r"(af[mf][2]),
                          "r"(af[mf][3]), "r"(b2), "r"(b3));
                }
            }
        }
        if (++s == 3) s = 0;
    }

    // ---------------- epilogue ----------------
    if (FUSED) {
        // symmetric half exchange:
        //   wg0 writes alpha acc for h==1 rows -> exA; emits h==0 rows.
        //   wg1 writes beta  acc for h==0 rows -> exB; emits h==1 rows.
        __syncthreads();
        float* exA = (float*)smh;                 // 128x132 fp32 (h==1 rows used)
        float* exB = (float*)smh + 128 * 132;     // 128x132 fp32 (h==0 rows used)
        {
            float* dst = (wg == 0) ? exA : exB;
            const int hw = (wg == 0) ? 1 : 0;     // which half this wg exports
#pragma unroll
            for (int mf = 0; mf < 2; mf++)
#pragma unroll
                for (int nf = 0; nf < 8; nf++) {
                    int rl = wm * 32 + mf * 16 + gid + hw * 8;
                    int col = wn * 64 + nf * 8 + tig * 2;
                    dst[rl * 132 + col] = acc[mf][nf][hw * 2];
                    dst[rl * 132 + col + 1] = acc[mf][nf][hw * 2 + 1];
                }
        }
        __syncthreads();
        {
            const int hk = (wg == 0) ? 0 : 1;     // half this wg emits
            const int bidx = (m0 >> 12);          // batch of this tile (Ldim=4096)
            const int l0 = m0 & (Ldim - 1);       // l offset of tile start
#pragma unroll
            for (int mf = 0; mf < 2; mf++)
#pragma unroll
                for (int nf = 0; nf < 8; nf++) {
                    int rl = wm * 32 + mf * 16 + gid + hk * 8;
                    int col = wn * 64 + nf * 8 + tig * 2;
                    size_t idx = (size_t)(m0 + rl) * Ddim + n0 + col;
                    float al0, al1, bt0, bt1;
                    if (wg == 0) {                // own alpha, smem beta
                        al0 = acc[mf][nf][0];
                        al1 = acc[mf][nf][1];
                        bt0 = exB[rl * 132 + col];
                        bt1 = exB[rl * 132 + col + 1];
                    } else {                      // smem alpha, own beta
                        al0 = exA[rl * 132 + col];
                        al1 = exA[rl * 132 + col + 1];
                        bt0 = acc[mf][nf][2];
                        bt1 = acc[mf][nf][3];
                    }
                    float a0 = sigmoidf_(al0 + bias1[n0 + col]);
                    float a1 = sigmoidf_(al1 + bias1[n0 + col + 1]);
                    float zb0 = bt0 + bias2[n0 + col];
                    float zb1 = bt1 + bias2[n0 + col + 1];
                    float be0 = zb0 * sigmoidf_(zb0);
                    float be1 = zb1 * sigmoidf_(zb1);
                    float w0 = sqrtf(fmaxf(1.0f - a0 * a0, 1e-6f));
                    float w1 = sqrtf(fmaxf(1.0f - a1 * a1, 1e-6f));
                    float2 vv = *(const float2*)(aux + idx);
                    float x0f = vv.x * be0 * w0;
                    float x1f = vv.y * be1 * w1;
                    __half2 xh = __floats2half2_rn(x0f, x1f);
                    *(float2*)(out1 + idx) = make_float2(a0, a1);
                    *(__half2*)(out2 + idx) = xh;
                    *(float2*)(out_v + idx) = vv;  // fused v pass-through

                    // ---- fused scan_p1: chunk (8-row) aggregate via shfl ----
                    // consistent with p3's replay: use fp16-rounded x
                    float2 xr = __half22float2(xh);
                    float X0 = xr.x, A0 = a0, X1 = xr.y, A1 = a1;
#pragma unroll
                    for (int st = 1; st < 8; st <<= 1) {
                        float pX0 = __shfl_up_sync(0xffffffffu, X0, st * 4);
                        float pA0 = __shfl_up_sync(0xffffffffu, A0, st * 4);
                        float pX1 = __shfl_up_sync(0xffffffffu, X1, st * 4);
                        float pA1 = __shfl_up_sync(0xffffffffu, A1, st * 4);
                        if (gid >= st) {
                            X0 = fmaf(A0, pX0, X0);
                            A0 *= pA0;
                            X1 = fmaf(A1, pX1, X1);
                            A1 *= pA1;
                        }
                    }
                    if (gid == 7) {
                        int l = l0 + wm * 32 + mf * 16 + hk * 8;  // chunk start
                        size_t oagg = ((size_t)bidx * NCHUNK + (l >> 3)) * Ddim +
                                      n0 + col;
                        *(float2*)(Xagg + oagg) = make_float2(X0, X1);
                        *(float2*)(Aagg + oagg) = make_float2(A0, A1);
                    }
                }
        }
    } else {
#pragma unroll
        for (int mf = 0; mf < 2; mf++)
#pragma unroll
            for (int nf = 0; nf < 8; nf++) {
                int rowl = wm * 32 + mf * 16 + gid;
                int col = wn * 64 + nf * 8 + tig * 2;
#pragma unroll
                for (int h = 0; h < 2; h++) {
                    int rl = rowl + h * 8;
                    size_t idx = (size_t)(m0 + rl) * Ddim + n0 + col;
                    float z0 = acc[mf][nf][h * 2] + bias1[n0 + col];
                    float z1 = acc[mf][nf][h * 2 + 1] + bias1[n0 + col + 1];
                    float2 cv = *(const float2*)(aux + idx);
                    *(float2*)(out1 + idx) = make_float2(
                        cv.x + z0 * sigmoidf_(z0), cv.y + z1 * sigmoidf_(z1));
                }
            }
    }
}

// ---------------- linear recurrence carry + replay (p1 fused into GEMM) ------
__global__ void scan_p2(const float* __restrict__ Xagg,
                        const float* __restrict__ Aagg,
                        float* __restrict__ carry) {
    int i = blockIdx.x * blockDim.x + threadIdx.x;
    int b = i / Ddim, d = i % Ddim;
    float h = 0.0f;
#pragma unroll 8
    for (int c = 0; c < NCHUNK; c++) {
        size_t o = ((size_t)b * NCHUNK + c) * Ddim + d;
        carry[o] = h;
        h = fmaf(Aagg[o], h, Xagg[o]);
    }
}

__global__ void scan_p3(const float* __restrict__ a, const __half* __restrict__ x,
                        const float* __restrict__ carry,
                        const float* __restrict__ out_in,
                        __half* __restrict__ f, float* __restrict__ out_out) {
    int d = (blockIdx.x * blockDim.x + threadIdx.x) * 2;
    int c = blockIdx.y, b = blockIdx.z;
    size_t base = ((size_t)b * Ldim + (size_t)c * CLEN) * Ddim + d;
    size_t o = ((size_t)b * NCHUNK + c) * Ddim + d;
    float2 hc = *(const float2*)(carry + o);
    float h0 = hc.x, h1 = hc.y;
#pragma unroll
    for (int t = 0; t < CLEN; t++) {
        size_t i = base + (size_t)t * Ddim;
        float2 at = *(const float2*)(a + i);
        float2 xt = __half22float2(*(const __half2*)(x + i));
        float2 ov = *(const float2*)(out_in + i);
        h0 = fmaf(at.x, h0, xt.x);
        h1 = fmaf(at.y, h1, xt.y);
        *(__half2*)(f + i) = __floats2half2_rn(h0, h1);
        *(float2*)(out_out + i) = make_float2(ov.x + h0, ov.y + h1);
    }
}

// ---------------- launch ------------------------------------------------------
extern "C" void kernel_launch(void* const* d_in, const int* in_sizes, int n_in,
                              void* d_out, int out_size) {
    const float* v       = (const float*)d_in[0];
    const float* ctx     = (const float*)d_in[1];
    const float* outp    = (const float*)d_in[2];
    const float* al      = (const float*)d_in[3];
    const float* gr      = (const float*)d_in[4];
    const float* W_alpha = (const float*)d_in[5];
    const float* b_alpha = (const float*)d_in[6];
    const float* W_beta  = (const float*)d_in[7];
    const float* b_beta  = (const float*)d_in[8];
    const float* W_ctx   = (const float*)d_in[9];
    const float* b_ctx   = (const float*)d_in[10];

    float* o_v   = (float*)d_out;
    float* o_ctx = o_v + BLD;
    float* o_out = o_ctx + BLD;
    float* o_al  = o_out + BLD;

    __half *p_norm, *p_x, *p_f, *p_W;
    float *p_a, *p_X, *p_A, *p_c;
    cudaGetSymbolAddress((void**)&p_norm, g_norm);
    cudaGetSymbolAddress((void**)&p_a, g_alpha);
    cudaGetSymbolAddress((void**)&p_x, g_x);
    cudaGetSymbolAddress((void**)&p_f, g_f);
    cudaGetSymbolAddress((void**)&p_X, g_Xagg);
    cudaGetSymbolAddress((void**)&p_A, g_Aagg);
    cudaGetSymbolAddress((void**)&p_c, g_carry);
    cudaGetSymbolAddress((void**)&p_W, g_Wt);
    __half* p_wa = p_W;
    __half* p_wb = p_W + (size_t)Ddim * Ddim;
    __half* p_wc = p_W + 2 * (size_t)Ddim * Ddim;

    const int SMEMF = 3 * 3 * TILE_H * 2;  // 165888 B
    const int SMEMS = 3 * 2 * TILE_H * 2;  // 110592 B
    cudaFuncSetAttribute(gemm_mma<true>,
                         cudaFuncAttributeMaxDynamicSharedMemorySize, SMEMF);
    cudaFuncSetAttribute(gemm_mma<false>,
                         cudaFuncAttributeMaxDynamicSharedMemorySize, SMEMS);

    // weight transposes (fp16, [N][K]) — all three in one launch
    dim3 tgrid(Ddim / 32, Ddim / 32, 3), tblk(32, 8);
    transpose_kernel<<<tgrid, tblk>>>(W_alpha, W_beta, W_ctx, p_W);

    // 1) ctx_norm (fp16) + fused alpha_logits pass-through
    rms_kernel<<<Mrows, 256>>>(ctx, gr, p_norm, al, o_al);

    // 2) fused alpha+beta GEMM + split gate epilogue + scan aggregates
    dim3 ggrid(Ddim / 128, Mrows / 128);  // (8, 128)
    gemm_mma<true><<<ggrid, 512, SMEMF>>>(p_norm, p_wa, p_wb, b_alpha, b_beta,
                                          v, p_a, p_x, o_v, p_X, p_A);

    // 3) linear recurrence carries + replay (p1 fused into GEMM epilogue)
    scan_p2<<<(Bdim * Ddim) / 256, 256>>>(p_X, p_A, p_c);
    dim3 sgrid(Ddim / 512, NCHUNK, Bdim);  // (2, 512, 4)
    scan_p3<<<sgrid, 256>>>(p_a, p_x, p_c, outp, p_f, o_out);

    // 4) ctx residual GEMM (fused bias+silu+add) with ctx L2 prefetch
    gemm_mma<false><<<ggrid, 256, SMEMS>>>(p_f, p_wc, nullptr, b_ctx, nullptr,
                                           ctx, o_ctx, nullptr, nullptr,
                                           nullptr, nullptr);
}

// round 17
// speedup vs baseline: 1.0890x; 1.0890x over previous
#include <cuda_runtime.h>
#include <cuda_fp16.h>
#include <cstdint>

// Problem shape (fixed by the dataset)
#define Bdim 4
#define Ldim 4096
#define Ddim 1024
#define Mrows (Bdim * Ldim)          // 16384
#define BLD ((size_t)Bdim * Ldim * Ddim)
#define NCHUNK 128
#define CLEN (Ldim / NCHUNK)         // 32
#define KDIM 1024
#define BKT 64
#define NKT (KDIM / BKT)             // 16
#define RS 72                        // smem row stride in halves (LDSM conflict-free)
#define TILE_H (128 * RS)            // halves per smem tile (9216)

// ---------------- scratch (static device arrays; no allocation) -------------
__device__ __half g_norm[(size_t)Mrows * Ddim];  // ctx_norm (fp16)
__device__ __half g_u[(size_t)Mrows * Ddim];     // u = 1 - alpha (fp16, rel-precise)
__device__ __half g_x[(size_t)Mrows * Ddim];     // gated recurrence input x_t (fp16)
__device__ __half g_f[(size_t)Mrows * Ddim];     // fetched (fp16, GEMM3 input)
__device__ float  g_Xagg[(size_t)Bdim * NCHUNK * Ddim];
__device__ float  g_Aagg[(size_t)Bdim * NCHUNK * Ddim];
__device__ float  g_carry[(size_t)Bdim * NCHUNK * Ddim];
__device__ __half g_Wt[3][(size_t)Ddim * Ddim];  // transposed fp16 weights [N][K]

__device__ __forceinline__ float sigmoidf_(float z) {
    return 1.0f / (1.0f + __expf(-z));
}
__device__ __forceinline__ uint32_t smem_u32(const void* p) {
    return (uint32_t)__cvta_generic_to_shared(p);
}
#define CP16(dst, src) \
    asm volatile("cp.async.cg.shared.global [%0], [%1], 16;\n" ::"r"(dst), "l"(src))
#define LDSM4(r0, r1, r2, r3, a)                                             \
    asm volatile("ldmatrix.sync.aligned.m8n8.x4.shared.b16 {%0,%1,%2,%3}, [%4];" \
                 : "=r"(r0), "=r"(r1), "=r"(r2), "=r"(r3) : "r"(a))

// ------- rmsnorm (fp16 output) + fused alpha_logits pass-through copy --------
__global__ void rms_kernel(const float* __restrict__ ctx,
                           const float* __restrict__ g,
                           __half* __restrict__ o,
                           const float* __restrict__ al,
                           float* __restrict__ o_al) {
    int row = blockIdx.x, tid = threadIdx.x;
    const float4* src = (const float4*)(ctx + (size_t)row * Ddim);
    const float4* asrc = (const float4*)(al + (size_t)row * Ddim);
    float4 xv = src[tid];
    float4 av = asrc[tid];  // independent load stream
    float ss = xv.x * xv.x + xv.y * xv.y + xv.z * xv.z + xv.w * xv.w;
#pragma unroll
    for (int off = 16; off > 0; off >>= 1)
        ss += __shfl_xor_sync(0xffffffffu, ss, off);
    __shared__ float ws[8];
    if ((tid & 31) == 0) ws[tid >> 5] = ss;
    ((float4*)(o_al + (size_t)row * Ddim))[tid] = av;  // copy while waiting
    __syncthreads();
    float tot = ws[0] + ws[1] + ws[2] + ws[3] + ws[4] + ws[5] + ws[6] + ws[7];
    float r = rsqrtf(tot * (1.0f / Ddim) + 1e-6f);
    float4 gv = ((const float4*)g)[tid];
    __half2 h01 = __floats2half2_rn(xv.x * r * gv.x, xv.y * r * gv.y);
    __half2 h23 = __floats2half2_rn(xv.z * r * gv.z, xv.w * r * gv.w);
    __half2* dst = (__half2*)(o + (size_t)row * Ddim);
    dst[tid * 2] = h01;
    dst[tid * 2 + 1] = h23;
}

// -------- weight transpose ([K,N] fp32 -> [N,K] fp16), all 3 in one launch ---
__global__ void transpose_kernel(const float* __restrict__ W0,
                                 const float* __restrict__ W1,
                                 const float* __restrict__ W2,
                                 __half* __restrict__ Wt) {
    __shared__ float tile[32][33];
    const float* W = (blockIdx.z == 0) ? W0 : (blockIdx.z == 1) ? W1 : W2;
    __half* Wo = Wt + (size_t)blockIdx.z * Ddim * Ddim;
    int x = blockIdx.x * 32 + threadIdx.x;
    int y = blockIdx.y * 32 + threadIdx.y;
#pragma unroll
    for (int j = 0; j < 32; j += 8)
        tile[threadIdx.y + j][threadIdx.x] = W[(size_t)(y + j) * Ddim + x];
    __syncthreads();
    int nx = blockIdx.y * 32 + threadIdx.x;
    int ny = blockIdx.x * 32 + threadIdx.y;
#pragma unroll
    for (int j = 0; j < 32; j += 8)
        Wo[(size_t)(ny + j) * Ddim + nx] = __float2half_rn(tile[threadIdx.x][threadIdx.y + j]);
}

// ================= FP16 mma.sync GEMM (m16n8k16, ldmatrix, BKT=64) ===========
// R6-proven config: 3 stages, SMEM K-minor row stride RS=72 halves.
// FUSED (512 thr): wg0 -> C1 = A*W1t, wg1 -> C2 = A*W2t; aux (v) L2-prefetched;
//   symmetric split epilogue: wg0 emits h==0 rows, wg1 emits h==1 rows.
//   outputs: out_u = fp16(1 - alpha); out2 = fp16(x); out_v = aux copy.
// !FUSED (256 thr): out1 = aux + silu(C1 + b1); ctx tile L2-prefetched.
template <bool FUSED>
__global__ void __launch_bounds__(FUSED ? 512 : 256, FUSED ? 1 : 2) gemm_mma(
    const __half* __restrict__ A, const __half* __restrict__ W1t,
    const __half* __restrict__ W2t,
    const float* __restrict__ bias1, const float* __restrict__ bias2,
    const float* __restrict__ aux,
    float* __restrict__ out1, __half* __restrict__ out_u,
    __half* __restrict__ out2, float* __restrict__ out_v) {
    constexpr int NT = FUSED ? 512 : 256;
    constexpr int NTILES = FUSED ? 3 : 2;
    constexpr int STAGE_H = NTILES * TILE_H;
    extern __shared__ __half smh[];

    const int tid = threadIdx.x;
    const int warp = tid >> 5, lane = tid & 31;
    const int wg = FUSED ? (warp >> 3) : 0;   // warpgroup (0/1)
    const int w8 = warp & 7;
    const int wm = w8 >> 1, wn = w8 & 1;      // 4x2 warp grid over 128x128
    const int gid = lane >> 2, tig = lane & 3;
    const int m0 = blockIdx.y * 128, n0 = blockIdx.x * 128;

    float acc[2][8][4];
#pragma unroll
    for (int i = 0; i < 2; i++)
#pragma unroll
        for (int j = 0; j < 8; j++)
#pragma unroll
            for (int k = 0; k < 4; k++) acc[i][j][k] = 0.0f;

    // ---- ldmatrix lane-address offsets (halves, relative to tile, excl. ko)
    const int lq = lane >> 3, lr = lane & 7;
    uint32_t a_loff[2], b_loff[4];
#pragma unroll
    for (int mf = 0; mf < 2; mf++)
        a_loff[mf] = (uint32_t)((wm * 32 + mf * 16 + lr + (lq & 1) * 8) * RS +
                                (lq >> 1) * 8);
#pragma unroll
    for (int p = 0; p < 4; p++)
        b_loff[p] = (uint32_t)((wn * 64 + p * 16 + lr + (lq >> 1) * 8) * RS +
                               (lq & 1) * 8);

    // warm L2 with the aux tile (v for FUSED, ctx for !FUSED): 512 x 128B lines
    {
#pragma unroll
        for (int q = 0; q < 512 / NT; q++) {
            int i = tid + q * NT;
            int row = i >> 2, c = (i & 3) * 32;
            asm volatile("prefetch.global.L2 [%0];" ::
                         "l"(aux + (size_t)(m0 + row) * Ddim + n0 + c));
        }
    }

    // 1024 16B-chunks per tile (128 rows x 8 chunks of 8 halves)
    auto ld_tile = [&](const __half* gsrc, __half* sdst, int row_off, int k0) {
#pragma unroll
        for (int j = 0; j < 1024 / NT; j++) {
            int i = tid + j * NT;
            int row = i >> 3, c = i & 7;
            CP16(smem_u32(sdst + row * RS + c * 8),
                 gsrc + (size_t)(row_off + row) * KDIM + k0 + c * 8);
        }
    };
    auto load_stage = [&](int kt, int s) {
        const int k0 = kt * BKT;
        __half* sb = smh + s * STAGE_H;
        ld_tile(A, sb, m0, k0);
        ld_tile(W1t, sb + TILE_H, n0, k0);
        if (FUSED) ld_tile(W2t, sb + 2 * TILE_H, n0, k0);
        asm volatile("cp.async.commit_group;\n");
    };

    load_stage(0, 0);
    load_stage(1, 1);

    const uint32_t smbase = smem_u32(smh);
    int s = 0;
    for (int kt = 0; kt < NKT; kt++) {
        if (kt >= NKT - 1)
            asm volatile("cp.async.wait_group 0;\n");
        else
            asm volatile("cp.async.wait_group 1;\n");
        __syncthreads();
        if (kt + 2 < NKT) {
            int s2 = s + 2;
            if (s2 >= 3) s2 -= 3;
            load_stage(kt + 2, s2);
        }

        const uint32_t a_base = smbase + s * (STAGE_H * 2);
        const uint32_t b_base = a_base + (1 + wg) * (TILE_H * 2);
#pragma unroll
        for (int ks = 0; ks < 4; ks++) {
            const int ko2 = ks * 32;  // k offset in bytes (16 halves)
            uint32_t af[2][4];
#pragma unroll
            for (int mf = 0; mf < 2; mf++)
                LDSM4(af[mf][0], af[mf][1], af[mf][2], af[mf][3],
                      a_base + a_loff[mf] * 2 + ko2);
#pragma unroll
            for (int p = 0; p < 4; p++) {
                uint32_t b0, b1, b2, b3;
                LDSM4(b0, b1, b2, b3, b_base + b_loff[p] * 2 + ko2);
#pragma unroll
                for (int mf = 0; mf < 2; mf++) {
                    asm volatile(
                        "mma.sync.aligned.m16n8k16.row.col.f32.f16.f16.f32 "
                        "{%0,%1,%2,%3}, {%4,%5,%6,%7}, {%8,%9}, {%0,%1,%2,%3};\n"
                        : "+f"(acc[mf][2 * p][0]), "+f"(acc[mf][2 * p][1]),
                          "+f"(acc[mf][2 * p][2]), "+f"(acc[mf][2 * p][3])
                        : "r"(af[mf][0]), "r"(af[mf][1]), "r"(af[mf][2]),
                          "r"(af[mf][3]), "r"(b0), "r"(b1));
                    asm volatile(
                        "mma.sync.aligned.m16n8k16.row.col.f32.f16.f16.f32 "
                        "{%0,%1,%2,%3}, {%4,%5,%6,%7}, {%8,%9}, {%0,%1,%2,%3};\n"
                        : "+f"(acc[mf][2 * p + 1][0]), "+f"(acc[mf][2 * p + 1][1]),
                          "+f"(acc[mf][2 * p + 1][2]), "+f"(acc[mf][2 * p + 1][3])
                        : "r"(af[mf][0]), "r"(af[mf][1]), "r"(af[mf][2]),
                          "r"(af[mf][3]), "r"(b2), "r"(b3));
                }
            }
        }
        if (++s == 3) s = 0;
    }

    // ---------------- epilogue ----------------
    if (FUSED) {
        // symmetric half exchange:
        //   wg0 writes alpha acc for h==1 rows -> exA; emits h==0 rows.
        //   wg1 writes beta  acc for h==0 rows -> exB; emits h==1 rows.
        __syncthreads();
        float* exA = (float*)smh;                 // 128x132 fp32 (h==1 rows used)
        float* exB = (float*)smh + 128 * 132;     // 128x132 fp32 (h==0 rows used)
        {
            float* dst = (wg == 0) ? exA : exB;
            const int hw = (wg == 0) ? 1 : 0;     // which half this wg exports
#pragma unroll
            for (int mf = 0; mf < 2; mf++)
#pragma unroll
                for (int nf = 0; nf < 8; nf++) {
                    int rl = wm * 32 + mf * 16 + gid + hw * 8;
                    int col = wn * 64 + nf * 8 + tig * 2;
                    dst[rl * 132 + col] = acc[mf][nf][hw * 2];
                    dst[rl * 132 + col + 1] = acc[mf][nf][hw * 2 + 1];
                }
        }
        __syncthreads();
        {
            const int hk = (wg == 0) ? 0 : 1;     // half this wg emits
#pragma unroll
            for (int mf = 0; mf < 2; mf++)
#pragma unroll
                for (int nf = 0; nf < 8; nf++) {
                    int rl = wm * 32 + mf * 16 + gid + hk * 8;
                    int col = wn * 64 + nf * 8 + tig * 2;
                    size_t idx = (size_t)(m0 + rl) * Ddim + n0 + col;
                    float al0, al1, bt0, bt1;
                    if (wg == 0) {                // own alpha, smem beta
                        al0 = acc[mf][nf][0];
                        al1 = acc[mf][nf][1];
                        bt0 = exB[rl * 132 + col];
                        bt1 = exB[rl * 132 + col + 1];
                    } else {                      // smem alpha, own beta
                        al0 = exA[rl * 132 + col];
                        al1 = exA[rl * 132 + col + 1];
                        bt0 = acc[mf][nf][2];
                        bt1 = acc[mf][nf][3];
                    }
                    float a0 = sigmoidf_(al0 + bias1[n0 + col]);
                    float a1 = sigmoidf_(al1 + bias1[n0 + col + 1]);
                    float zb0 = bt0 + bias2[n0 + col];
                    float zb1 = bt1 + bias2[n0 + col + 1];
                    float be0 = zb0 * sigmoidf_(zb0);
                    float be1 = zb1 * sigmoidf_(zb1);
                    float w0 = sqrtf(fmaxf(1.0f - a0 * a0, 1e-6f));
                    float w1 = sqrtf(fmaxf(1.0f - a1 * a1, 1e-6f));
                    float2 vv = *(const float2*)(aux + idx);
                    // u = 1 - alpha : relative precision where it matters
                    *(__half2*)(out_u + idx) =
                        __floats2half2_rn(1.0f - a0, 1.0f - a1);
                    *(__half2*)(out2 + idx) =
                        __floats2half2_rn(vv.x * be0 * w0, vv.y * be1 * w1);
                    *(float2*)(out_v + idx) = vv;  // fused v pass-through
                }
        }
    } else {
#pragma unroll
        for (int mf = 0; mf < 2; mf++)
#pragma unroll
            for (int nf = 0; nf < 8; nf++) {
                int rowl = wm * 32 + mf * 16 + gid;
                int col = wn * 64 + nf * 8 + tig * 2;
#pragma unroll
                for (int h = 0; h < 2; h++) {
                    int rl = rowl + h * 8;
                    size_t idx = (size_t)(m0 + rl) * Ddim + n0 + col;
                    float z0 = acc[mf][nf][h * 2] + bias1[n0 + col];
                    float z1 = acc[mf][nf][h * 2 + 1] + bias1[n0 + col + 1];
                    float2 cv = *(const float2*)(aux + idx);
                    *(float2*)(out1 + idx) = make_float2(
                        cv.x + z0 * sigmoidf_(z0), cv.y + z1 * sigmoidf_(z1));
                }
            }
    }
}

// ---------------- chunked linear recurrence (h_t = a_t h_{t-1} + x_t) --------
// a reconstructed as 1 - u (u fp16); 2 d-lanes per thread.
__global__ void scan_p1(const __half* __restrict__ u, const __half* __restrict__ x,
                        float* __restrict__ Xagg, float* __restrict__ Aagg) {
    int d = (blockIdx.x * blockDim.x + threadIdx.x) * 2;
    int c = blockIdx.y, b = blockIdx.z;
    size_t base = ((size_t)b * Ldim + (size_t)c * CLEN) * Ddim + d;
    float X0 = 0.0f, X1 = 0.0f, A0 = 1.0f, A1 = 1.0f;
#pragma unroll 8
    for (int t = 0; t < CLEN; t++) {
        float2 ut = __half22float2(*(const __half2*)(u + base + (size_t)t * Ddim));
        float2 xt = __half22float2(*(const __half2*)(x + base + (size_t)t * Ddim));
        float a0 = 1.0f - ut.x, a1 = 1.0f - ut.y;
        X0 = fmaf(a0, X0, xt.x);
        X1 = fmaf(a1, X1, xt.y);
        A0 *= a0;
        A1 *= a1;
    }
    size_t o = ((size_t)b * NCHUNK + c) * Ddim + d;
    *(float2*)(Xagg + o) = make_float2(X0, X1);
    *(float2*)(Aagg + o) = make_float2(A0, A1);
}

__global__ void scan_p2(const float* __restrict__ Xagg,
                        const float* __restrict__ Aagg,
                        float* __restrict__ carry) {
    int i = blockIdx.x * blockDim.x + threadIdx.x;
    int b = i / Ddim, d = i % Ddim;
    float h = 0.0f;
#pragma unroll 8
    for (int c = 0; c < NCHUNK; c++) {
        size_t o = ((size_t)b * NCHUNK + c) * Ddim + d;
        carry[o] = h;
        h = fmaf(Aagg[o], h, Xagg[o]);
    }
}

__global__ void scan_p3(const __half* __restrict__ u, const __half* __restrict__ x,
                        const float* __restrict__ carry,
                        const float* __restrict__ out_in,
                        __half* __restrict__ f, float* __restrict__ out_out) {
    int d = (blockIdx.x * blockDim.x + threadIdx.x) * 2;
    int c = blockIdx.y, b = blockIdx.z;
    size_t base = ((size_t)b * Ldim + (size_t)c * CLEN) * Ddim + d;
    size_t o = ((size_t)b * NCHUNK + c) * Ddim + d;
    float2 hc = *(const float2*)(carry + o);
    float h0 = hc.x, h1 = hc.y;
#pragma unroll 8
    for (int t = 0; t < CLEN; t++) {
        size_t i = base + (size_t)t * Ddim;
        float2 ut = __half22float2(*(const __half2*)(u + i));
        float2 xt = __half22float2(*(const __half2*)(x + i));
        float2 ov = *(const float2*)(out_in + i);
        h0 = fmaf(1.0f - ut.x, h0, xt.x);
        h1 = fmaf(1.0f - ut.y, h1, xt.y);
        *(__half2*)(f + i) = __floats2half2_rn(h0, h1);
        *(float2*)(out_out + i) = make_float2(ov.x + h0, ov.y + h1);
    }
}

// ---------------- launch ------------------------------------------------------
extern "C" void kernel_launch(void* const* d_in, const int* in_sizes, int n_in,
                              void* d_out, int out_size) {
    const float* v       = (const float*)d_in[0];
    const float* ctx     = (const float*)d_in[1];
    const float* outp    = (const float*)d_in[2];
    const float* al      = (const float*)d_in[3];
    const float* gr      = (const float*)d_in[4];
    const float* W_alpha = (const float*)d_in[5];
    const float* b_alpha = (const float*)d_in[6];
    const float* W_beta  = (const float*)d_in[7];
    const float* b_beta  = (const float*)d_in[8];
    const float* W_ctx   = (const float*)d_in[9];
    const float* b_ctx   = (const float*)d_in[10];

    float* o_v   = (float*)d_out;
    float* o_ctx = o_v + BLD;
    float* o_out = o_ctx + BLD;
    float* o_al  = o_out + BLD;

    __half *p_norm, *p_u, *p_x, *p_f, *p_W;
    float *p_X, *p_A, *p_c;
    cudaGetSymbolAddress((void**)&p_norm, g_norm);
    cudaGetSymbolAddress((void**)&p_u, g_u);
    cudaGetSymbolAddress((void**)&p_x, g_x);
    cudaGetSymbolAddress((void**)&p_f, g_f);
    cudaGetSymbolAddress((void**)&p_X, g_Xagg);
    cudaGetSymbolAddress((void**)&p_A, g_Aagg);
    cudaGetSymbolAddress((void**)&p_c, g_carry);
    cudaGetSymbolAddress((void**)&p_W, g_Wt);
    __half* p_wa = p_W;
    __half* p_wb = p_W + (size_t)Ddim * Ddim;
    __half* p_wc = p_W + 2 * (size_t)Ddim * Ddim;

    const int SMEMF = 3 * 3 * TILE_H * 2;  // 165888 B
    const int SMEMS = 3 * 2 * TILE_H * 2;  // 110592 B
    cudaFuncSetAttribute(gemm_mma<true>,
                         cudaFuncAttributeMaxDynamicSharedMemorySize, SMEMF);
    cudaFuncSetAttribute(gemm_mma<false>,
                         cudaFuncAttributeMaxDynamicSharedMemorySize, SMEMS);

    // weight transposes (fp16, [N][K]) — all three in one launch
    dim3 tgrid(Ddim / 32, Ddim / 32, 3), tblk(32, 8);
    transpose_kernel<<<tgrid, tblk>>>(W_alpha, W_beta, W_ctx, p_W);

    // 1) ctx_norm (fp16) + fused alpha_logits pass-through
    rms_kernel<<<Mrows, 256>>>(ctx, gr, p_norm, al, o_al);

    // 2) fused alpha+beta GEMM + split gate epilogue -> u fp16, x fp16, o_v
    dim3 ggrid(Ddim / 128, Mrows / 128);  // (8, 128)
    gemm_mma<true><<<ggrid, 512, SMEMF>>>(p_norm, p_wa, p_wb, b_alpha, b_beta,
                                          v, nullptr, p_u, p_x, o_v);

    // 3) linear recurrence over L (3-pass; 2 lanes/thread; 128 chunks)
    dim3 sgrid(Ddim / 512, NCHUNK, Bdim);  // (2, 128, 4)
    scan_p1<<<sgrid, 256>>>(p_u, p_x, p_X, p_A);
    scan_p2<<<(Bdim * Ddim) / 256, 256>>>(p_X, p_A, p_c);
    scan_p3<<<sgrid, 256>>>(p_u, p_x, p_c, outp, p_f, o_out);

    // 4) ctx residual GEMM (fused bias+silu+add) with ctx L2 prefetch
    gemm_mma<false><<<ggrid, 256, SMEMS>>>(p_f, p_wc, nullptr, b_ctx, nullptr,
                                           ctx, o_ctx, nullptr, nullptr, nullptr);
}